// round 7
// baseline (speedup 1.0000x reference)
#include <cuda_runtime.h>

#define K_CODES 16384
#define NSAMP   4096
#define DIM     14
#define HW      1024
#define Q_ELEMS 57344            // 4 * 14 * 1024
#define WPB     8                // warps (= samples) per block
#define NBLK    (NSAMP / WPB)    // 512 blocks

// Module-load zero-initialized; every call restores zeros behind itself so
// each execution (eager correctness run or graph replay) starts identically.
__device__ __align__(16) float g_avg[K_CODES];
__device__ float g_ent_sum;
__device__ int   g_done;

__device__ __forceinline__ float warp_sum(float v) {
#pragma unroll
    for (int off = 16; off > 0; off >>= 1)
        v += __shfl_xor_sync(0xffffffffu, v, off);
    return v;
}

// ---------------------------------------------------------------------------
// Single kernel, NO grid barrier.
// Phase 1 (warp per sample): coalesced block-staged load of the 8 samples'
//   14 channels; ballot -> big-endian index; shuffle reductions -> norm and
//   the EXACT closed-form entropy (softmax over +-1 codes factorizes into
//   per-dim Bernoullis): a_j = 400|xn_j|, logS = sum log(1+e^-a_j),
//   H = logS + sum a_j e^-a_j/(1+e^-a_j).
//   Survivor scatter into g_avg: lane = subset mask of dims with a_j < 30
//   (dropped probs < e^-30, below fp32 noise in the reference itself).
// Tail: each block fences + takes a ticket and EXITS; the block drawing the
//   last ticket (all scatters provably performed) folds the 16K histogram
//   alone (float4 loads, __logf, re-zeroing), writes el, resets state.
// ---------------------------------------------------------------------------
__global__ __launch_bounds__(32 * WPB) void lfq_fused(const float* __restrict__ x,
                                                      float* __restrict__ out) {
    __shared__ float sv[DIM][WPB + 1];   // staged x (padded: conflict-free)
    __shared__ float sq[DIM][WPB + 1];   // staged q
    __shared__ float sc[WPB][DIM];       // flip costs of small dims
    __shared__ int   st[WPB][DIM];       // index-bit toggles
    __shared__ float sidxf[WPB];         // index as float
    __shared__ float wents[WPB];
    __shared__ int   s_last;

    const int tid  = threadIdx.x;
    const int wid  = tid >> 5;
    const int lane = tid & 31;
    const int s0   = blockIdx.x * WPB;   // 8 consecutive samples, same b
    const int b    = s0 >> 10;
    const int n0   = s0 & (HW - 1);

    // ---- coalesced staged load: 112 threads, 14 sectors total ----
    if (tid < DIM * WPB) {
        const int j  = tid >> 3;         // channel
        const int dn = tid & 7;          // sample-in-block
        sv[j][dn] = x[(b * DIM + j) * HW + n0 + dn];
    }
    __syncthreads();

    // ---- per-warp closed-form work ----
    const float v = (lane < DIM) ? sv[lane][wid] : 0.0f;
    if (lane < DIM) sq[lane][wid] = (v > 0.0f) ? 1.0f : -1.0f;

    const float inv = rsqrtf(warp_sum(v * v));

    const unsigned bal = __ballot_sync(0xffffffffu, v > 0.0f) & 0x3FFFu;
    const int idx = (int)(__brev(bal) >> 18);    // big-endian bit order
    if (lane == 0) sidxf[wid] = (float)idx;

    const float a = (lane < DIM) ? 400.0f * fabsf(v) * inv : 1e30f;
    const float e = __expf(-a);                  // exactly 0 for pad lanes
    const float logS = warp_sum(__logf(1.0f + e));
    const float ent  = logS + warp_sum(a * e / (1.0f + e));
    if (lane == 0) wents[wid] = ent;

    // rank the "small" (flippable) dims into shared
    const bool small = (lane < DIM) && (a < 30.0f);
    const unsigned bm = __ballot_sync(0xffffffffu, small);
    const int m = __popc(bm);
    if (small) {
        const int rank = __popc(bm & ((1u << lane) - 1u));
        sc[wid][rank] = a;
        st[wid][rank] = 1 << (13 - lane);
    }
    __syncwarp();

    // survivor scatter: lane = subset mask (single pass for ~95% of samples)
    const float invS = __expf(-logS);
    const int nm = 1 << m;
    for (int mask = lane; mask < nm; mask += 32) {
        float c = 0.0f;
        int tog = 0;
        for (int j = 0; j < m; j++)
            if ((mask >> j) & 1) { c += sc[wid][j]; tog ^= st[wid][j]; }
        if (c < 30.0f)
            atomicAdd(&g_avg[idx ^ tog], __expf(-c) * invS);
    }

    // ---- coalesced staged writes: q and indices ----
    __syncthreads();
    if (tid < DIM * WPB) {
        const int j  = tid >> 3;
        const int dn = tid & 7;
        out[(b * DIM + j) * HW + n0 + dn] = sq[j][dn];
    }
    if (tid < WPB) out[Q_ELEMS + 1 + s0 + tid] = sidxf[tid];

    // block entropy partial + ticket
    if (tid < WPB) {
        float t = wents[tid];
#pragma unroll
        for (int off = WPB / 2; off > 0; off >>= 1)
            t += __shfl_xor_sync((1u << WPB) - 1u, t, off);
        if (tid == 0) {
            atomicAdd(&g_ent_sum, t);
            __threadfence();                       // release scatters + ent
            const int ticket = atomicAdd(&g_done, 1);
            s_last = (ticket == NBLK - 1) ? 1 : 0;
        }
    }
    __syncthreads();
    if (!s_last) return;                           // 511 blocks exit, no wait

    // ---- last block: fold the whole histogram (all scatters performed) ----
    __threadfence();                               // acquire
    const float4 z4 = make_float4(0.f, 0.f, 0.f, 0.f);
    float acc = 0.0f;
#pragma unroll
    for (int i = 0; i < K_CODES / 4 / (32 * WPB); i++) {   // 16 iters
        const int i4 = i * (32 * WPB) + tid;               // coalesced
        float4 a4 = reinterpret_cast<float4*>(g_avg)[i4];
        reinterpret_cast<float4*>(g_avg)[i4] = z4;         // restore zeros
        const float sN = 1.0f / (float)NSAMP;
        acc += (a4.x * sN) * __logf(a4.x * sN + 1e-9f)
             + (a4.y * sN) * __logf(a4.y * sN + 1e-9f)
             + (a4.z * sN) * __logf(a4.z * sN + 1e-9f)
             + (a4.w * sN) * __logf(a4.w * sN + 1e-9f);
    }
    __shared__ float wred[WPB];
    acc = warp_sum(acc);
    if (lane == 0) wred[wid] = acc;
    __syncthreads();
    if (tid < WPB) {
        float t = wred[tid];
#pragma unroll
        for (int off = WPB / 2; off > 0; off >>= 1)
            t += __shfl_xor_sync((1u << WPB) - 1u, t, off);
        if (tid == 0) {
            const float es = atomicAdd(&g_ent_sum, 0.0f);
            // el = entro_mean - mean_entro = es/N + sum a*log(a+eps)
            out[Q_ELEMS] = es * (1.0f / (float)NSAMP) + t;
            g_ent_sum = 0.0f;
            g_done    = 0;
        }
    }
}

extern "C" void kernel_launch(void* const* d_in, const int* in_sizes, int n_in,
                              void* d_out, int out_size) {
    const float* x = (const float*)d_in[0];
    float* out = (float*)d_out;
    lfq_fused<<<NBLK, 32 * WPB>>>(x, out);
}

// round 8
// speedup vs baseline: 1.3088x; 1.3088x over previous
#include <cuda_runtime.h>

#define K_CODES 16384
#define NSAMP   4096
#define DIM     14
#define HW      1024
#define Q_ELEMS 57344            // 4 * 14 * 1024
#define WPB     8                // warps (= samples) per block, kernel A
#define HBLK    32               // blocks, kernel B
#define HTHR    128              // threads, kernel B (32*128 float4 = 16384)

// Module-load zero-initialized; every call restores zeros behind itself so
// each execution (eager correctness run or graph replay) starts identically.
__device__ __align__(16) float g_avg[K_CODES];
__device__ float g_ent_sum;
__device__ float g_hist_sum;
__device__ int   g_done;

__device__ __forceinline__ float warp_sum(float v) {
#pragma unroll
    for (int off = 16; off > 0; off >>= 1)
        v += __shfl_xor_sync(0xffffffffu, v, off);
    return v;
}

// ---------------------------------------------------------------------------
// Kernel A (identical structure to the measured-best R4 kernel):
// ONE WARP PER SAMPLE. lane j<14 owns dim j. Ballot -> big-endian index;
// shuffle reductions -> norm and the EXACT closed-form entropy (the softmax
// over +-1 codes factorizes into per-dim Bernoullis):
//   a_j = 400|xn_j|,  logS = sum log(1+e^-a_j),  H = logS + sum a_j*e_j/(1+e_j)
// Survivor scatter into g_avg: lane = subset mask of dims with a_j < 30
// (dropped probs < e^-30, below fp32 noise in the reference itself).
// ---------------------------------------------------------------------------
__global__ __launch_bounds__(32 * WPB) void lfq_main(const float* __restrict__ x,
                                                     float* __restrict__ out) {
    __shared__ float sc[WPB][DIM];
    __shared__ int   st[WPB][DIM];
    __shared__ float wents[WPB];

    const int wid  = threadIdx.x >> 5;
    const int lane = threadIdx.x & 31;
    const int s    = blockIdx.x * WPB + wid;    // sample id
    const int b    = s >> 10;
    const int n    = s & (HW - 1);

    float v = 0.0f;
    if (lane < DIM) {
        v = x[(b * DIM + lane) * HW + n];
        out[(b * DIM + lane) * HW + n] = (v > 0.0f) ? 1.0f : -1.0f;
    }

    const float inv = rsqrtf(warp_sum(v * v));

    const unsigned bal = __ballot_sync(0xffffffffu, v > 0.0f) & 0x3FFFu;
    const int idx = (int)(__brev(bal) >> 18);    // big-endian bit order
    if (lane == 0) out[Q_ELEMS + 1 + s] = (float)idx;

    // closed-form softmax stats (fast-math: 2^-21 rel err vs 1e-3 budget)
    const float a = (lane < DIM) ? 400.0f * fabsf(v) * inv : 1e30f;
    const float e = __expf(-a);                  // exactly 0 for pad lanes
    const float logS = warp_sum(__logf(1.0f + e));
    const float ent  = logS + warp_sum(__fdividef(a * e, 1.0f + e));
    if (lane == 0) wents[wid] = ent;

    // rank the "small" (flippable) dims into shared
    const bool small = (lane < DIM) && (a < 30.0f);
    const unsigned bm = __ballot_sync(0xffffffffu, small);
    const int m = __popc(bm);
    if (small) {
        const int rank = __popc(bm & ((1u << lane) - 1u));
        sc[wid][rank] = a;
        st[wid][rank] = 1 << (13 - lane);
    }
    __syncwarp();

    // survivor scatter: lane = subset mask (one pass for ~95% of samples)
    const float invS = __expf(-logS);
    const int nm = 1 << m;
    for (int mask = lane; mask < nm; mask += 32) {
        float c = 0.0f;
        int tog = 0;
        for (int j = 0; j < m; j++)
            if ((mask >> j) & 1) { c += sc[wid][j]; tog ^= st[wid][j]; }
        if (c < 30.0f)
            atomicAdd(&g_avg[idx ^ tog], __expf(-c) * invS);
    }

    // block-level entropy reduction -> one atomic per block
    __syncthreads();
    if (threadIdx.x < WPB) {
        float t = wents[threadIdx.x];
#pragma unroll
        for (int off = WPB / 2; off > 0; off >>= 1)
            t += __shfl_xor_sync((1u << WPB) - 1u, t, off);
        if (threadIdx.x == 0) atomicAdd(&g_ent_sum, t);
    }
}

// ---------------------------------------------------------------------------
// Kernel B: 32 blocks x 128 threads, ONE float4 histogram chunk per thread.
// Accumulates sum_k avg*log(avg+eps) (MUFU __logf), zeroes the histogram
// behind itself; the block drawing the last ticket combines the scalars into
// el and resets all state for the next graph replay.
// ---------------------------------------------------------------------------
__global__ __launch_bounds__(HTHR) void lfq_hist(float* __restrict__ out) {
    __shared__ float wsum[HTHR / 32];
    const int tid = threadIdx.x;
    const int i4  = blockIdx.x * HTHR + tid;     // float4 index, coalesced

    const float sN = 1.0f / (float)NSAMP;
    float4 a4 = reinterpret_cast<float4*>(g_avg)[i4];
    reinterpret_cast<float4*>(g_avg)[i4] = make_float4(0.f, 0.f, 0.f, 0.f);
    float ms = (a4.x * sN) * __logf(a4.x * sN + 1e-9f)
             + (a4.y * sN) * __logf(a4.y * sN + 1e-9f)
             + (a4.z * sN) * __logf(a4.z * sN + 1e-9f)
             + (a4.w * sN) * __logf(a4.w * sN + 1e-9f);

    ms = warp_sum(ms);
    if ((tid & 31) == 0) wsum[tid >> 5] = ms;
    __syncthreads();
    if (tid < HTHR / 32) {
        float t = wsum[tid];
#pragma unroll
        for (int off = HTHR / 64; off > 0; off >>= 1)
            t += __shfl_xor_sync((1u << (HTHR / 32)) - 1u, t, off);
        if (tid == 0) {
            atomicAdd(&g_hist_sum, t);
            __threadfence();
            const int d = atomicAdd(&g_done, 1);
            if (d == HBLK - 1) {
                const float hs = atomicAdd(&g_hist_sum, 0.0f);
                const float es = atomicAdd(&g_ent_sum, 0.0f);
                // el = entro_mean - mean_entro = es/N + sum a*log(a+eps)
                out[Q_ELEMS] = es * (1.0f / (float)NSAMP) + hs;
                g_hist_sum = 0.0f;
                g_ent_sum  = 0.0f;
                g_done     = 0;
            }
        }
    }
}

extern "C" void kernel_launch(void* const* d_in, const int* in_sizes, int n_in,
                              void* d_out, int out_size) {
    const float* x = (const float*)d_in[0];
    float* out = (float*)d_out;

    lfq_main<<<NSAMP / WPB, 32 * WPB>>>(x, out);
    lfq_hist<<<HBLK, HTHR>>>(out);
}